// round 2
// baseline (speedup 1.0000x reference)
#include <cuda_runtime.h>
#include <cuda_bf16.h>
#include <cstdint>

// ---------------- problem constants ----------------
#define NN      200000
#define NE      1600000
#define NG      5000
#define FDIM    128        // per-head feature dim (all layers)
#define MAXH    3
#define MAXM    (MAXH*FDIM)   // 384
#define ETOT    (NE + NN)     // edges incl. self loops

// ---------------- scratch (__device__ globals; no allocs allowed) ----------------
__device__ float    g_h   [(size_t)NN * MAXM];   // gemm output (per-node per-head features)
__device__ float    g_agg [(size_t)NN * MAXM];   // aggregation accumulator
__device__ float    g_feat[(size_t)NN * MAXM];   // layer input features (after bias+lrelu)
__device__ float    g_ebuf[(size_t)ETOT * MAXH]; // per-edge logits / exp
__device__ float    g_als [(size_t)NN * MAXH];
__device__ float    g_ald [(size_t)NN * MAXH];
__device__ unsigned g_menc[(size_t)NN * MAXH];   // encoded segment max
__device__ float    g_den [(size_t)NN * MAXH];
__device__ float    g_pool[(size_t)NG * FDIM];
__device__ int      g_cnt [NG];

// ---------------- helpers ----------------
__device__ __forceinline__ float lrelu(float v) { return v > 0.0f ? v : 0.2f * v; }

// order-preserving float <-> uint encoding (for atomicMax on floats incl. negatives)
__device__ __forceinline__ unsigned enc_f(float f) {
    unsigned u = __float_as_uint(f);
    return (u & 0x80000000u) ? ~u : (u | 0x80000000u);
}
__device__ __forceinline__ float dec_f(unsigned u) {
    unsigned b = (u & 0x80000000u) ? (u ^ 0x80000000u) : ~u;
    return __uint_as_float(b);
}

// ---------------- zero kernels ----------------
__global__ void zero_f(float* p, size_t n) {
    size_t i = (size_t)blockIdx.x * blockDim.x + threadIdx.x;
    size_t stride = (size_t)gridDim.x * blockDim.x;
    for (; i < n; i += stride) p[i] = 0.0f;
}
__global__ void zero_u(unsigned* p, size_t n) {
    size_t i = (size_t)blockIdx.x * blockDim.x + threadIdx.x;
    size_t stride = (size_t)gridDim.x * blockDim.x;
    for (; i < n; i += stride) p[i] = 0u;   // enc sentinel: any real value encodes > 0
}
__global__ void zero_i(int* p, size_t n) {
    size_t i = (size_t)blockIdx.x * blockDim.x + threadIdx.x;
    size_t stride = (size_t)gridDim.x * blockDim.x;
    for (; i < n; i += stride) p[i] = 0;
}

// ---------------- GEMM: C[Nrows,M] = A[Nrows,K] @ B[K,M], all row-major fp32 ----------------
// 64x64 tile, BK=16, 256 threads, 4x4 register microtile.
// Assumes Nrows%64==0, M%64==0, K%16==0 (true here: 200000, {128,384}, {128,384}).
#define BM 64
#define BN 64
#define BK 16
__global__ __launch_bounds__(256) void gemm_kernel(const float* __restrict__ A,
                                                   const float* __restrict__ B,
                                                   float* __restrict__ C,
                                                   int Nrows, int K, int M) {
    __shared__ float As[BK][BM];
    __shared__ float Bs[BK][BN];

    const int bm = blockIdx.y * BM;
    const int bn = blockIdx.x * BN;
    const int t  = threadIdx.x;
    const int tx = t & 15;
    const int ty = t >> 4;

    const int arow  = t >> 2;          // 0..63
    const int acol4 = (t & 3) << 2;    // 0,4,8,12
    const int brow  = t >> 4;          // 0..15
    const int bcol4 = (t & 15) << 2;   // 0..60

    float acc[4][4] = {};

    for (int k0 = 0; k0 < K; k0 += BK) {
        float4 av = *(const float4*)&A[(size_t)(bm + arow) * K + k0 + acol4];
        As[acol4 + 0][arow] = av.x;
        As[acol4 + 1][arow] = av.y;
        As[acol4 + 2][arow] = av.z;
        As[acol4 + 3][arow] = av.w;
        float4 bv = *(const float4*)&B[(size_t)(k0 + brow) * M + bn + bcol4];
        *(float4*)&Bs[brow][bcol4] = bv;
        __syncthreads();
#pragma unroll
        for (int k = 0; k < BK; ++k) {
            float a[4], b[4];
#pragma unroll
            for (int i = 0; i < 4; ++i) a[i] = As[k][ty * 4 + i];
#pragma unroll
            for (int j = 0; j < 4; ++j) b[j] = Bs[k][tx * 4 + j];
#pragma unroll
            for (int i = 0; i < 4; ++i)
#pragma unroll
                for (int j = 0; j < 4; ++j) acc[i][j] = fmaf(a[i], b[j], acc[i][j]);
        }
        __syncthreads();
    }
#pragma unroll
    for (int i = 0; i < 4; ++i) {
        float4 v = make_float4(acc[i][0], acc[i][1], acc[i][2], acc[i][3]);
        *(float4*)&C[(size_t)(bm + ty * 4 + i) * M + bn + tx * 4] = v;
    }
}

// ---------------- attention coefficients: als[n,h]=<h[n,h,:],a_s[h,:]>, same for ald ----------
__global__ void attn_kernel(const float* __restrict__ h,
                            const float* __restrict__ a_s,
                            const float* __restrict__ a_d,
                            float* __restrict__ als, float* __restrict__ ald,
                            int Nn, int H) {
    int w = (blockIdx.x * blockDim.x + threadIdx.x) >> 5;
    int lane = threadIdx.x & 31;
    if (w >= Nn * H) return;
    int node = w / H;
    int head = w - node * H;
    const float4* hp = (const float4*)(h + ((size_t)node * H + head) * FDIM);
    const float4* sp = (const float4*)(a_s + head * FDIM);
    const float4* dp = (const float4*)(a_d + head * FDIM);
    float4 hv = hp[lane], sv = sp[lane], dv = dp[lane];
    float s = hv.x * sv.x + hv.y * sv.y + hv.z * sv.z + hv.w * sv.w;
    float d = hv.x * dv.x + hv.y * dv.y + hv.z * dv.z + hv.w * dv.w;
#pragma unroll
    for (int o = 16; o > 0; o >>= 1) {
        s += __shfl_xor_sync(0xffffffffu, s, o);
        d += __shfl_xor_sync(0xffffffffu, d, o);
    }
    if (lane == 0) { als[w] = s; ald[w] = d; }
}

// ---------------- edge pass 1: logits + segment max ----------------
__global__ void edge_pass1(const int* __restrict__ srcs, const int* __restrict__ dsts,
                           int E, int Nn, int H,
                           const float* __restrict__ als, const float* __restrict__ ald,
                           float* __restrict__ ebuf, unsigned* __restrict__ menc) {
    int e = blockIdx.x * blockDim.x + threadIdx.x;
    int Et = E + Nn;
    if (e >= Et) return;
    int s, d;
    if (e < E) { s = srcs[e]; d = dsts[e]; }
    else       { s = d = e - E; }
    for (int h = 0; h < H; ++h) {
        float v = lrelu(als[(size_t)s * H + h] + ald[(size_t)d * H + h]);
        ebuf[(size_t)e * H + h] = v;
        atomicMax(&menc[(size_t)d * H + h], enc_f(v));
    }
}

// ---------------- edge pass 2: exp + segment sum ----------------
__global__ void edge_pass2(const int* __restrict__ srcs, const int* __restrict__ dsts,
                           int E, int Nn, int H,
                           const unsigned* __restrict__ menc,
                           float* __restrict__ ebuf, float* __restrict__ den) {
    int e = blockIdx.x * blockDim.x + threadIdx.x;
    int Et = E + Nn;
    if (e >= Et) return;
    int d;
    if (e < E) d = dsts[e];
    else       d = e - E;
    for (int h = 0; h < H; ++h) {
        float m = dec_f(menc[(size_t)d * H + h]);
        float ex = expf(ebuf[(size_t)e * H + h] - m);
        ebuf[(size_t)e * H + h] = ex;
        atomicAdd(&den[(size_t)d * H + h], ex);
    }
}

// ---------------- edge pass 3: weighted scatter-add (warp per edge, v4 red) --------------
__global__ void edge_pass3(const int* __restrict__ srcs, const int* __restrict__ dsts,
                           int E, int Nn, int H,
                           const float* __restrict__ hbuf, const float* __restrict__ ebuf,
                           const float* __restrict__ den, float* __restrict__ agg) {
    int w = (blockIdx.x * blockDim.x + threadIdx.x) >> 5;
    int lane = threadIdx.x & 31;
    int Et = E + Nn;
    if (w >= Et) return;
    int s, d;
    if (w < E) { s = srcs[w]; d = dsts[w]; }
    else       { s = d = w - E; }
    const float4* hs = (const float4*)(hbuf + (size_t)s * H * FDIM);
    float4*       ag = (float4*)(agg  + (size_t)d * H * FDIM);
    for (int h = 0; h < H; ++h) {
        float alpha = ebuf[(size_t)w * H + h] / (den[(size_t)d * H + h] + 1e-16f);
        float4 v = hs[h * 32 + lane];
        v.x *= alpha; v.y *= alpha; v.z *= alpha; v.w *= alpha;
        float4* p = ag + h * 32 + lane;
        asm volatile("red.global.add.v4.f32 [%0], {%1,%2,%3,%4};"
                     :: "l"(p), "f"(v.x), "f"(v.y), "f"(v.z), "f"(v.w) : "memory");
    }
}

// ---------------- bias + leaky relu into next-layer features ----------------
__global__ void finalize_kernel(const float* __restrict__ agg, const float* __restrict__ b,
                                float* __restrict__ feat, size_t total, int M) {
    size_t i = (size_t)blockIdx.x * blockDim.x + threadIdx.x;
    size_t stride = (size_t)gridDim.x * blockDim.x;
    for (; i < total; i += stride) {
        int m = (int)(i % (size_t)M);
        feat[i] = lrelu(agg[i] + b[m]);
    }
}

// ---------------- layer-3 finalize + pooling ----------------
__global__ void pool_kernel(const float* __restrict__ agg, const float* __restrict__ b3,
                            const int* __restrict__ batch, float* __restrict__ pool,
                            int Nn) {
    size_t i = (size_t)blockIdx.x * blockDim.x + threadIdx.x;
    if (i >= (size_t)Nn * FDIM) return;
    int n = (int)(i >> 7);
    int f = (int)(i & 127);
    float v = lrelu(agg[i] + b3[f]);
    atomicAdd(&pool[(size_t)batch[n] * FDIM + f], v);
}
__global__ void count_kernel(const int* __restrict__ batch, int* __restrict__ cnt, int Nn) {
    int n = blockIdx.x * blockDim.x + threadIdx.x;
    if (n < Nn) atomicAdd(&cnt[batch[n]], 1);
}
__global__ void out_kernel(const float* __restrict__ pool, const int* __restrict__ cnt,
                           float* __restrict__ out, int G) {
    int i = blockIdx.x * blockDim.x + threadIdx.x;
    if (i >= G * FDIM) return;
    int g = i >> 7;
    float c = (float)max(cnt[g], 1);
    out[i] = pool[i] / c;
}

// ---------------- host orchestration ----------------
static void run_layer(const float* feat_in, const float* W, const float* a_s, const float* a_d,
                      int K, int H,
                      const int* srcs, const int* dsts, int E, int Nn,
                      float* hbuf, float* agg, float* ebuf, float* als, float* ald,
                      unsigned* menc, float* den) {
    int M = H * FDIM;
    dim3 ggrid(M / BN, Nn / BM);
    gemm_kernel<<<ggrid, 256>>>(feat_in, W, hbuf, Nn, K, M);

    long long nwt = (long long)Nn * H * 32;
    attn_kernel<<<(unsigned)((nwt + 255) / 256), 256>>>(hbuf, a_s, a_d, als, ald, Nn, H);

    zero_u<<<1024, 256>>>(menc, (size_t)Nn * H);
    zero_f<<<1024, 256>>>(den, (size_t)Nn * H);
    zero_f<<<8192, 256>>>(agg, (size_t)Nn * M);

    int Et = E + Nn;
    edge_pass1<<<(Et + 255) / 256, 256>>>(srcs, dsts, E, Nn, H, als, ald, ebuf, menc);
    edge_pass2<<<(Et + 255) / 256, 256>>>(srcs, dsts, E, Nn, H, menc, ebuf, den);
    long long p3t = (long long)Et * 32;
    edge_pass3<<<(unsigned)((p3t + 255) / 256), 256>>>(srcs, dsts, E, Nn, H, hbuf, ebuf, den, agg);
}

extern "C" void kernel_launch(void* const* d_in, const int* in_sizes, int n_in,
                              void* d_out, int out_size) {
    // inputs (metadata order): x, edge_index, batch, W1,a1s,a1d,b1, W2,a2s,a2d,b2, W3,a3s,a3d,b3
    // NOTE: JAX default config has x64 disabled -> edge_index/batch are int32.
    const float* x   = (const float*)d_in[0];
    const int*   ei  = (const int*)d_in[1];
    const int*   bat = (const int*)d_in[2];
    const float* W1  = (const float*)d_in[3];
    const float* a1s = (const float*)d_in[4];
    const float* a1d = (const float*)d_in[5];
    const float* b1  = (const float*)d_in[6];
    const float* W2  = (const float*)d_in[7];
    const float* a2s = (const float*)d_in[8];
    const float* a2d = (const float*)d_in[9];
    const float* b2  = (const float*)d_in[10];
    const float* W3  = (const float*)d_in[11];
    const float* a3s = (const float*)d_in[12];
    const float* a3d = (const float*)d_in[13];
    const float* b3  = (const float*)d_in[14];

    int Nn = in_sizes[0] / FDIM;     // 200000
    int E  = in_sizes[1] / 2;        // 1600000
    const int* srcs = ei;
    const int* dsts = ei + E;

    float *hbuf, *agg, *feat, *ebuf, *als, *ald, *den, *pool;
    unsigned* menc;
    int* cnt;
    cudaGetSymbolAddress((void**)&hbuf, g_h);
    cudaGetSymbolAddress((void**)&agg,  g_agg);
    cudaGetSymbolAddress((void**)&feat, g_feat);
    cudaGetSymbolAddress((void**)&ebuf, g_ebuf);
    cudaGetSymbolAddress((void**)&als,  g_als);
    cudaGetSymbolAddress((void**)&ald,  g_ald);
    cudaGetSymbolAddress((void**)&menc, g_menc);
    cudaGetSymbolAddress((void**)&den,  g_den);
    cudaGetSymbolAddress((void**)&pool, g_pool);
    cudaGetSymbolAddress((void**)&cnt,  g_cnt);

    // ---- layer 1: IN=128 -> 3 heads x 128, concat ----
    run_layer(x, W1, a1s, a1d, 128, 3, srcs, dsts, E, Nn,
              hbuf, agg, ebuf, als, ald, menc, den);
    finalize_kernel<<<8192, 256>>>(agg, b1, feat, (size_t)Nn * 384, 384);

    // ---- layer 2: 384 -> 3 heads x 128, concat ----
    run_layer(feat, W2, a2s, a2d, 384, 3, srcs, dsts, E, Nn,
              hbuf, agg, ebuf, als, ald, menc, den);
    finalize_kernel<<<8192, 256>>>(agg, b2, feat, (size_t)Nn * 384, 384);

    // ---- layer 3: 384 -> 1 head x 128, mean(=identity for 1 head) ----
    run_layer(feat, W3, a3s, a3d, 384, 1, srcs, dsts, E, Nn,
              hbuf, agg, ebuf, als, ald, menc, den);

    // ---- pooling ----
    zero_f<<<1024, 256>>>(pool, (size_t)NG * FDIM);
    zero_i<<<32, 256>>>(cnt, (size_t)NG);
    pool_kernel<<<((size_t)Nn * FDIM + 255) / 256, 256>>>(agg, b3, bat, pool, Nn);
    count_kernel<<<(Nn + 255) / 256, 256>>>(bat, cnt, Nn);
    out_kernel<<<(NG * FDIM + 255) / 256, 256>>>(pool, cnt, (float*)d_out, NG);
}

// round 3
// speedup vs baseline: 1.1637x; 1.1637x over previous
#include <cuda_runtime.h>
#include <cuda_bf16.h>
#include <cstdint>

// ---------------- problem constants ----------------
#define NN      200000
#define NE      1600000
#define NG      5000
#define FDIM    128
#define MAXH    3
#define MAXM    (MAXH*FDIM)   // 384
#define ETOT    (NE + NN)

// ---------------- scratch ----------------
__device__ float    g_h   [(size_t)NN * MAXM];
__device__ float    g_agg [(size_t)NN * MAXM];
__device__ float    g_feat[(size_t)NN * MAXM];
__device__ float    g_ebuf[(size_t)ETOT * MAXH];
__device__ float    g_als [(size_t)NN * MAXH];
__device__ float    g_ald [(size_t)NN * MAXH];
__device__ unsigned g_menc[(size_t)NN * MAXH];
__device__ float    g_den [(size_t)NN * MAXH];
__device__ float    g_pool[(size_t)NG * FDIM];
__device__ int      g_cnt [NG];

// ---------------- helpers ----------------
__device__ __forceinline__ float lrelu(float v) { return v > 0.0f ? v : 0.2f * v; }

__device__ __forceinline__ unsigned enc_f(float f) {
    unsigned u = __float_as_uint(f);
    return (u & 0x80000000u) ? ~u : (u | 0x80000000u);
}
__device__ __forceinline__ float dec_f(unsigned u) {
    unsigned b = (u & 0x80000000u) ? (u ^ 0x80000000u) : ~u;
    return __uint_as_float(b);
}

__device__ __forceinline__ unsigned f2tf32(float f) {
    unsigned u;
    asm("cvt.rna.tf32.f32 %0, %1;" : "=r"(u) : "f"(f));
    return u;
}

__device__ __forceinline__ void mma_tf32(float* d, const unsigned* a, const unsigned* b) {
    asm volatile(
        "mma.sync.aligned.m16n8k8.row.col.f32.tf32.tf32.f32 "
        "{%0,%1,%2,%3}, {%4,%5,%6,%7}, {%8,%9}, {%0,%1,%2,%3};"
        : "+f"(d[0]), "+f"(d[1]), "+f"(d[2]), "+f"(d[3])
        : "r"(a[0]), "r"(a[1]), "r"(a[2]), "r"(a[3]), "r"(b[0]), "r"(b[1]));
}

// ---------------- zero kernels ----------------
__global__ void zero_f(float* p, size_t n) {
    size_t i = (size_t)blockIdx.x * blockDim.x + threadIdx.x;
    size_t stride = (size_t)gridDim.x * blockDim.x;
    for (; i < n; i += stride) p[i] = 0.0f;
}
__global__ void zero_u(unsigned* p, size_t n) {
    size_t i = (size_t)blockIdx.x * blockDim.x + threadIdx.x;
    size_t stride = (size_t)gridDim.x * blockDim.x;
    for (; i < n; i += stride) p[i] = 0u;
}
__global__ void zero_i(int* p, size_t n) {
    size_t i = (size_t)blockIdx.x * blockDim.x + threadIdx.x;
    size_t stride = (size_t)gridDim.x * blockDim.x;
    for (; i < n; i += stride) p[i] = 0;
}

// ================= tensor-core GEMM: 3xTF32 (fp32-accurate) =================
// C[Nrows,M] = A[Nrows,K] @ B[K,M]; row-major.
// CTA tile 64x64, BK=32, 128 threads (4 warps as 2x2, each warp 32x32).
// Requires Nrows%64==0 (200000=3125*64), M%64==0, K%32==0.
#define GBM 64
#define GBN 64
#define GBK 32
#define A_ST 36   // padded stride: frag addr = 36*m + k -> bank (4m+k)%32 unique
#define B_ST 72   // padded stride: frag addr = 72*k + n -> bank (8k+n)%32 unique

__global__ __launch_bounds__(128) void gemm_tf32_kernel(const float* __restrict__ A,
                                                        const float* __restrict__ B,
                                                        float* __restrict__ C,
                                                        int Nrows, int K, int M) {
    __shared__ unsigned Ah[GBM][A_ST];
    __shared__ unsigned Al[GBM][A_ST];
    __shared__ unsigned Bh[GBK][B_ST];
    __shared__ unsigned Bl[GBK][B_ST];

    const int bm = blockIdx.y * GBM;
    const int bn = blockIdx.x * GBN;
    const int t  = threadIdx.x;
    const int w  = t >> 5;
    const int l  = t & 31;
    const int g  = l >> 2;     // group id (row within fragment)
    const int tg = l & 3;      // thread-in-group
    const int mw = (w & 1) * 32;
    const int nw = (w >> 1) * 32;

    float acc[2][4][4];
#pragma unroll
    for (int i = 0; i < 2; ++i)
#pragma unroll
        for (int j = 0; j < 4; ++j)
#pragma unroll
            for (int q = 0; q < 4; ++q) acc[i][j][q] = 0.0f;

    for (int k0 = 0; k0 < K; k0 += GBK) {
        // ---- load + split A chunk (64x32) ----
#pragma unroll
        for (int i = 0; i < 4; ++i) {
            int lin = (i * 128 + t) * 4;           // 2048 floats total
            int r = lin >> 5, c = lin & 31;
            float4 v = *(const float4*)&A[(size_t)(bm + r) * K + k0 + c];
            unsigned h0 = f2tf32(v.x), h1 = f2tf32(v.y), h2 = f2tf32(v.z), h3 = f2tf32(v.w);
            unsigned l0 = f2tf32(v.x - __uint_as_float(h0));
            unsigned l1 = f2tf32(v.y - __uint_as_float(h1));
            unsigned l2 = f2tf32(v.z - __uint_as_float(h2));
            unsigned l3 = f2tf32(v.w - __uint_as_float(h3));
            *(uint4*)&Ah[r][c] = make_uint4(h0, h1, h2, h3);
            *(uint4*)&Al[r][c] = make_uint4(l0, l1, l2, l3);
        }
        // ---- load + split B chunk (32x64) ----
#pragma unroll
        for (int i = 0; i < 4; ++i) {
            int lin = (i * 128 + t) * 4;
            int r = lin >> 6, c = lin & 63;
            float4 v = *(const float4*)&B[(size_t)(k0 + r) * M + bn + c];
            unsigned h0 = f2tf32(v.x), h1 = f2tf32(v.y), h2 = f2tf32(v.z), h3 = f2tf32(v.w);
            unsigned l0 = f2tf32(v.x - __uint_as_float(h0));
            unsigned l1 = f2tf32(v.y - __uint_as_float(h1));
            unsigned l2 = f2tf32(v.z - __uint_as_float(h2));
            unsigned l3 = f2tf32(v.w - __uint_as_float(h3));
            *(uint4*)&Bh[r][c] = make_uint4(h0, h1, h2, h3);
            *(uint4*)&Bl[r][c] = make_uint4(l0, l1, l2, l3);
        }
        __syncthreads();

#pragma unroll
        for (int ks = 0; ks < 4; ++ks) {
            const int kk = ks * 8;
            unsigned afh[2][4], afl[2][4], bfh[4][2], bfl[4][2];
#pragma unroll
            for (int mf = 0; mf < 2; ++mf) {
                int r0 = mw + mf * 16;
                afh[mf][0] = Ah[r0 + g    ][kk + tg    ];
                afh[mf][1] = Ah[r0 + g + 8][kk + tg    ];
                afh[mf][2] = Ah[r0 + g    ][kk + tg + 4];
                afh[mf][3] = Ah[r0 + g + 8][kk + tg + 4];
                afl[mf][0] = Al[r0 + g    ][kk + tg    ];
                afl[mf][1] = Al[r0 + g + 8][kk + tg    ];
                afl[mf][2] = Al[r0 + g    ][kk + tg + 4];
                afl[mf][3] = Al[r0 + g + 8][kk + tg + 4];
            }
#pragma unroll
            for (int nf = 0; nf < 4; ++nf) {
                int c0 = nw + nf * 8;
                bfh[nf][0] = Bh[kk + tg    ][c0 + g];
                bfh[nf][1] = Bh[kk + tg + 4][c0 + g];
                bfl[nf][0] = Bl[kk + tg    ][c0 + g];
                bfl[nf][1] = Bl[kk + tg + 4][c0 + g];
            }
#pragma unroll
            for (int mf = 0; mf < 2; ++mf)
#pragma unroll
                for (int nf = 0; nf < 4; ++nf) {
                    mma_tf32(acc[mf][nf], afh[mf], bfl[nf]);
                    mma_tf32(acc[mf][nf], afl[mf], bfh[nf]);
                    mma_tf32(acc[mf][nf], afh[mf], bfh[nf]);
                }
        }
        __syncthreads();
    }

    // ---- epilogue: D fragment -> C ----
#pragma unroll
    for (int mf = 0; mf < 2; ++mf)
#pragma unroll
        for (int nf = 0; nf < 4; ++nf) {
            int row = bm + mw + mf * 16 + g;
            int col = bn + nw + nf * 8 + 2 * tg;
            *(float2*)&C[(size_t)row * M + col] =
                make_float2(acc[mf][nf][0], acc[mf][nf][1]);
            *(float2*)&C[(size_t)(row + 8) * M + col] =
                make_float2(acc[mf][nf][2], acc[mf][nf][3]);
        }
}

// ---------------- attention coefficients ----------------
__global__ void attn_kernel(const float* __restrict__ h,
                            const float* __restrict__ a_s,
                            const float* __restrict__ a_d,
                            float* __restrict__ als, float* __restrict__ ald,
                            int Nn, int H) {
    int w = (blockIdx.x * blockDim.x + threadIdx.x) >> 5;
    int lane = threadIdx.x & 31;
    if (w >= Nn * H) return;
    int node = w / H;
    int head = w - node * H;
    const float4* hp = (const float4*)(h + ((size_t)node * H + head) * FDIM);
    const float4* sp = (const float4*)(a_s + head * FDIM);
    const float4* dp = (const float4*)(a_d + head * FDIM);
    float4 hv = hp[lane], sv = sp[lane], dv = dp[lane];
    float s = hv.x * sv.x + hv.y * sv.y + hv.z * sv.z + hv.w * sv.w;
    float d = hv.x * dv.x + hv.y * dv.y + hv.z * dv.z + hv.w * dv.w;
#pragma unroll
    for (int o = 16; o > 0; o >>= 1) {
        s += __shfl_xor_sync(0xffffffffu, s, o);
        d += __shfl_xor_sync(0xffffffffu, d, o);
    }
    if (lane == 0) { als[w] = s; ald[w] = d; }
}

// ---------------- edge pass 1: logits + segment max ----------------
__global__ void edge_pass1(const int* __restrict__ srcs, const int* __restrict__ dsts,
                           int E, int Nn, int H,
                           const float* __restrict__ als, const float* __restrict__ ald,
                           float* __restrict__ ebuf, unsigned* __restrict__ menc) {
    int e = blockIdx.x * blockDim.x + threadIdx.x;
    int Et = E + Nn;
    if (e >= Et) return;
    int s, d;
    if (e < E) { s = srcs[e]; d = dsts[e]; }
    else       { s = d = e - E; }
    for (int h = 0; h < H; ++h) {
        float v = lrelu(als[(size_t)s * H + h] + ald[(size_t)d * H + h]);
        ebuf[(size_t)e * H + h] = v;
        atomicMax(&menc[(size_t)d * H + h], enc_f(v));
    }
}

// ---------------- edge pass 2: exp + segment sum ----------------
__global__ void edge_pass2(const int* __restrict__ srcs, const int* __restrict__ dsts,
                           int E, int Nn, int H,
                           const unsigned* __restrict__ menc,
                           float* __restrict__ ebuf, float* __restrict__ den) {
    int e = blockIdx.x * blockDim.x + threadIdx.x;
    int Et = E + Nn;
    if (e >= Et) return;
    int d;
    if (e < E) d = dsts[e];
    else       d = e - E;
    for (int h = 0; h < H; ++h) {
        float m = dec_f(menc[(size_t)d * H + h]);
        float ex = expf(ebuf[(size_t)e * H + h] - m);
        ebuf[(size_t)e * H + h] = ex;
        atomicAdd(&den[(size_t)d * H + h], ex);
    }
}

// ---------------- edge pass 3: weighted scatter-add ----------------
__global__ void edge_pass3(const int* __restrict__ srcs, const int* __restrict__ dsts,
                           int E, int Nn, int H,
                           const float* __restrict__ hbuf, const float* __restrict__ ebuf,
                           const float* __restrict__ den, float* __restrict__ agg) {
    int w = (blockIdx.x * blockDim.x + threadIdx.x) >> 5;
    int lane = threadIdx.x & 31;
    int Et = E + Nn;
    if (w >= Et) return;
    int s, d;
    if (w < E) { s = srcs[w]; d = dsts[w]; }
    else       { s = d = w - E; }
    const float4* hs = (const float4*)(hbuf + (size_t)s * H * FDIM);
    float4*       ag = (float4*)(agg  + (size_t)d * H * FDIM);
    for (int h = 0; h < H; ++h) {
        float alpha = ebuf[(size_t)w * H + h] / (den[(size_t)d * H + h] + 1e-16f);
        float4 v = hs[h * 32 + lane];
        v.x *= alpha; v.y *= alpha; v.z *= alpha; v.w *= alpha;
        float4* p = ag + h * 32 + lane;
        asm volatile("red.global.add.v4.f32 [%0], {%1,%2,%3,%4};"
                     :: "l"(p), "f"(v.x), "f"(v.y), "f"(v.z), "f"(v.w) : "memory");
    }
}

// ---------------- bias + leaky relu ----------------
__global__ void finalize_kernel(const float* __restrict__ agg, const float* __restrict__ b,
                                float* __restrict__ feat, size_t total, int M) {
    size_t i = (size_t)blockIdx.x * blockDim.x + threadIdx.x;
    size_t stride = (size_t)gridDim.x * blockDim.x;
    for (; i < total; i += stride) {
        int m = (int)(i % (size_t)M);
        feat[i] = lrelu(agg[i] + b[m]);
    }
}

// ---------------- pooling ----------------
__global__ void pool_kernel(const float* __restrict__ agg, const float* __restrict__ b3,
                            const int* __restrict__ batch, float* __restrict__ pool,
                            int Nn) {
    size_t i = (size_t)blockIdx.x * blockDim.x + threadIdx.x;
    if (i >= (size_t)Nn * FDIM) return;
    int n = (int)(i >> 7);
    int f = (int)(i & 127);
    float v = lrelu(agg[i] + b3[f]);
    atomicAdd(&pool[(size_t)batch[n] * FDIM + f], v);
}
__global__ void count_kernel(const int* __restrict__ batch, int* __restrict__ cnt, int Nn) {
    int n = blockIdx.x * blockDim.x + threadIdx.x;
    if (n < Nn) atomicAdd(&cnt[batch[n]], 1);
}
__global__ void out_kernel(const float* __restrict__ pool, const int* __restrict__ cnt,
                           float* __restrict__ out, int G) {
    int i = blockIdx.x * blockDim.x + threadIdx.x;
    if (i >= G * FDIM) return;
    int g = i >> 7;
    float c = (float)max(cnt[g], 1);
    out[i] = pool[i] / c;
}

// ---------------- host orchestration ----------------
static void run_layer(const float* feat_in, const float* W, const float* a_s, const float* a_d,
                      int K, int H,
                      const int* srcs, const int* dsts, int E, int Nn,
                      float* hbuf, float* agg, float* ebuf, float* als, float* ald,
                      unsigned* menc, float* den) {
    int M = H * FDIM;
    dim3 ggrid(M / GBN, Nn / GBM);
    gemm_tf32_kernel<<<ggrid, 128>>>(feat_in, W, hbuf, Nn, K, M);

    long long nwt = (long long)Nn * H * 32;
    attn_kernel<<<(unsigned)((nwt + 255) / 256), 256>>>(hbuf, a_s, a_d, als, ald, Nn, H);

    zero_u<<<1024, 256>>>(menc, (size_t)Nn * H);
    zero_f<<<1024, 256>>>(den, (size_t)Nn * H);
    zero_f<<<8192, 256>>>(agg, (size_t)Nn * M);

    int Et = E + Nn;
    edge_pass1<<<(Et + 255) / 256, 256>>>(srcs, dsts, E, Nn, H, als, ald, ebuf, menc);
    edge_pass2<<<(Et + 255) / 256, 256>>>(srcs, dsts, E, Nn, H, menc, ebuf, den);
    long long p3t = (long long)Et * 32;
    edge_pass3<<<(unsigned)((p3t + 255) / 256), 256>>>(srcs, dsts, E, Nn, H, hbuf, ebuf, den, agg);
}

extern "C" void kernel_launch(void* const* d_in, const int* in_sizes, int n_in,
                              void* d_out, int out_size) {
    const float* x   = (const float*)d_in[0];
    const int*   ei  = (const int*)d_in[1];
    const int*   bat = (const int*)d_in[2];
    const float* W1  = (const float*)d_in[3];
    const float* a1s = (const float*)d_in[4];
    const float* a1d = (const float*)d_in[5];
    const float* b1  = (const float*)d_in[6];
    const float* W2  = (const float*)d_in[7];
    const float* a2s = (const float*)d_in[8];
    const float* a2d = (const float*)d_in[9];
    const float* b2  = (const float*)d_in[10];
    const float* W3  = (const float*)d_in[11];
    const float* a3s = (const float*)d_in[12];
    const float* a3d = (const float*)d_in[13];
    const float* b3  = (const float*)d_in[14];

    int Nn = in_sizes[0] / FDIM;     // 200000
    int E  = in_sizes[1] / 2;        // 1600000
    const int* srcs = ei;
    const int* dsts = ei + E;

    float *hbuf, *agg, *feat, *ebuf, *als, *ald, *den, *pool;
    unsigned* menc;
    int* cnt;
    cudaGetSymbolAddress((void**)&hbuf, g_h);
    cudaGetSymbolAddress((void**)&agg,  g_agg);
    cudaGetSymbolAddress((void**)&feat, g_feat);
    cudaGetSymbolAddress((void**)&ebuf, g_ebuf);
    cudaGetSymbolAddress((void**)&als,  g_als);
    cudaGetSymbolAddress((void**)&ald,  g_ald);
    cudaGetSymbolAddress((void**)&menc, g_menc);
    cudaGetSymbolAddress((void**)&den,  g_den);
    cudaGetSymbolAddress((void**)&pool, g_pool);
    cudaGetSymbolAddress((void**)&cnt,  g_cnt);

    // ---- layer 1 ----
    run_layer(x, W1, a1s, a1d, 128, 3, srcs, dsts, E, Nn,
              hbuf, agg, ebuf, als, ald, menc, den);
    finalize_kernel<<<8192, 256>>>(agg, b1, feat, (size_t)Nn * 384, 384);

    // ---- layer 2 ----
    run_layer(feat, W2, a2s, a2d, 384, 3, srcs, dsts, E, Nn,
              hbuf, agg, ebuf, als, ald, menc, den);
    finalize_kernel<<<8192, 256>>>(agg, b2, feat, (size_t)Nn * 384, 384);

    // ---- layer 3 ----
    run_layer(feat, W3, a3s, a3d, 384, 1, srcs, dsts, E, Nn,
              hbuf, agg, ebuf, als, ald, menc, den);

    // ---- pooling ----
    zero_f<<<1024, 256>>>(pool, (size_t)NG * FDIM);
    zero_i<<<32, 256>>>(cnt, (size_t)NG);
    pool_kernel<<<((size_t)Nn * FDIM + 255) / 256, 256>>>(agg, b3, bat, pool, Nn);
    count_kernel<<<(Nn + 255) / 256, 256>>>(bat, cnt, Nn);
    out_kernel<<<(NG * FDIM + 255) / 256, 256>>>(pool, cnt, (float*)d_out, NG);
}

// round 4
// speedup vs baseline: 2.0790x; 1.7866x over previous
#include <cuda_runtime.h>
#include <cuda_bf16.h>
#include <cstdint>

// ---------------- problem constants ----------------
#define NN      200000
#define NE      1600000
#define NG      5000
#define FDIM    128
#define MAXH    3
#define MAXM    (MAXH*FDIM)   // 384
#define ETOT    (NE + NN)
#define SCAN_B  1024
#define SCAN_NB ((NN + SCAN_B - 1) / SCAN_B)   // 196

// ---------------- scratch ----------------
__device__ float g_h   [(size_t)NN * MAXM];
__device__ float g_feat[(size_t)NN * MAXM];
__device__ float g_als [(size_t)NN * MAXH];
__device__ float g_ald [(size_t)NN * MAXH];
__device__ float g_pool[(size_t)NG * FDIM];
__device__ int   g_cnt [NG];
__device__ int   g_deg [NN];
__device__ int   g_rowptr[NN + 1];
__device__ int   g_woff[NN];
__device__ int   g_bsum[256];
__device__ int   g_csrc[ETOT];

// ---------------- helpers ----------------
__device__ __forceinline__ float lrelu(float v) { return v > 0.0f ? v : 0.2f * v; }

__device__ __forceinline__ unsigned f2tf32(float f) {
    unsigned u;
    asm("cvt.rna.tf32.f32 %0, %1;" : "=r"(u) : "f"(f));
    return u;
}

__device__ __forceinline__ void mma_tf32(float* d, const unsigned* a, const unsigned* b) {
    asm volatile(
        "mma.sync.aligned.m16n8k8.row.col.f32.tf32.tf32.f32 "
        "{%0,%1,%2,%3}, {%4,%5,%6,%7}, {%8,%9}, {%0,%1,%2,%3};"
        : "+f"(d[0]), "+f"(d[1]), "+f"(d[2]), "+f"(d[3])
        : "r"(a[0]), "r"(a[1]), "r"(a[2]), "r"(a[3]), "r"(b[0]), "r"(b[1]));
}

// ---------------- small utility kernels ----------------
__global__ void zero_f(float* p, size_t n) {
    size_t i = (size_t)blockIdx.x * blockDim.x + threadIdx.x;
    size_t stride = (size_t)gridDim.x * blockDim.x;
    for (; i < n; i += stride) p[i] = 0.0f;
}
__global__ void zero_i(int* p, size_t n) {
    size_t i = (size_t)blockIdx.x * blockDim.x + threadIdx.x;
    size_t stride = (size_t)gridDim.x * blockDim.x;
    for (; i < n; i += stride) p[i] = 0;
}

// ================= CSR construction (by destination) =================
__global__ void deg_kernel(const int* __restrict__ dsts, int E, int Nn, int* __restrict__ deg) {
    int e = blockIdx.x * blockDim.x + threadIdx.x;
    int Et = E + Nn;
    if (e >= Et) return;
    int d = (e < E) ? dsts[e] : (e - E);
    atomicAdd(&deg[d], 1);
}

// per-block exclusive scan (1024 elems), writes exclusive values + block total
__global__ void scan1_kernel(const int* __restrict__ deg, int* __restrict__ excl,
                             int* __restrict__ bsum, int n) {
    __shared__ int sm[SCAN_B];
    int t = threadIdx.x;
    int gid = blockIdx.x * SCAN_B + t;
    int v = (gid < n) ? deg[gid] : 0;
    sm[t] = v;
    __syncthreads();
#pragma unroll
    for (int o = 1; o < SCAN_B; o <<= 1) {
        int u = (t >= o) ? sm[t - o] : 0;
        __syncthreads();
        sm[t] += u;
        __syncthreads();
    }
    if (gid < n) excl[gid] = sm[t] - v;
    if (t == SCAN_B - 1) bsum[blockIdx.x] = sm[t];
}

// exclusive scan of <=256 block sums, single block
__global__ void scan2_kernel(int* __restrict__ bsum, int nb) {
    __shared__ int sm[256];
    int t = threadIdx.x;
    int v = (t < nb) ? bsum[t] : 0;
    sm[t] = v;
    __syncthreads();
#pragma unroll
    for (int o = 1; o < 256; o <<= 1) {
        int u = (t >= o) ? sm[t - o] : 0;
        __syncthreads();
        sm[t] += u;
        __syncthreads();
    }
    if (t < nb) bsum[t] = sm[t] - v;
}

__global__ void scan3_kernel(int* __restrict__ rowptr, int* __restrict__ woff,
                             const int* __restrict__ bsum, int n, int Et) {
    int gid = blockIdx.x * SCAN_B + threadIdx.x;
    if (gid < n) {
        int v = rowptr[gid] + bsum[gid >> 10];
        rowptr[gid] = v;
        woff[gid] = v;
    }
    if (gid == 0) rowptr[n] = Et;
}

__global__ void scatter_kernel(const int* __restrict__ srcs, const int* __restrict__ dsts,
                               int E, int Nn, int* __restrict__ woff, int* __restrict__ csrc) {
    int e = blockIdx.x * blockDim.x + threadIdx.x;
    int Et = E + Nn;
    if (e >= Et) return;
    int s, d;
    if (e < E) { s = srcs[e]; d = dsts[e]; }
    else       { s = d = e - E; }
    int pos = atomicAdd(&woff[d], 1);
    csrc[pos] = s;
}

// ================= tensor-core GEMM: 3xTF32 =================
#define GBM 64
#define GBN 64
#define GBK 32
#define A_ST 36
#define B_ST 72

__global__ __launch_bounds__(128) void gemm_tf32_kernel(const float* __restrict__ A,
                                                        const float* __restrict__ B,
                                                        float* __restrict__ C,
                                                        int Nrows, int K, int M) {
    __shared__ unsigned Ah[GBM][A_ST];
    __shared__ unsigned Al[GBM][A_ST];
    __shared__ unsigned Bh[GBK][B_ST];
    __shared__ unsigned Bl[GBK][B_ST];

    const int bm = blockIdx.y * GBM;
    const int bn = blockIdx.x * GBN;
    const int t  = threadIdx.x;
    const int w  = t >> 5;
    const int l  = t & 31;
    const int g  = l >> 2;
    const int tg = l & 3;
    const int mw = (w & 1) * 32;
    const int nw = (w >> 1) * 32;

    float acc[2][4][4];
#pragma unroll
    for (int i = 0; i < 2; ++i)
#pragma unroll
        for (int j = 0; j < 4; ++j)
#pragma unroll
            for (int q = 0; q < 4; ++q) acc[i][j][q] = 0.0f;

    for (int k0 = 0; k0 < K; k0 += GBK) {
#pragma unroll
        for (int i = 0; i < 4; ++i) {
            int lin = (i * 128 + t) * 4;
            int r = lin >> 5, c = lin & 31;
            float4 v = *(const float4*)&A[(size_t)(bm + r) * K + k0 + c];
            unsigned h0 = f2tf32(v.x), h1 = f2tf32(v.y), h2 = f2tf32(v.z), h3 = f2tf32(v.w);
            unsigned l0 = f2tf32(v.x - __uint_as_float(h0));
            unsigned l1 = f2tf32(v.y - __uint_as_float(h1));
            unsigned l2 = f2tf32(v.z - __uint_as_float(h2));
            unsigned l3 = f2tf32(v.w - __uint_as_float(h3));
            *(uint4*)&Ah[r][c] = make_uint4(h0, h1, h2, h3);
            *(uint4*)&Al[r][c] = make_uint4(l0, l1, l2, l3);
        }
#pragma unroll
        for (int i = 0; i < 4; ++i) {
            int lin = (i * 128 + t) * 4;
            int r = lin >> 6, c = lin & 63;
            float4 v = *(const float4*)&B[(size_t)(k0 + r) * M + bn + c];
            unsigned h0 = f2tf32(v.x), h1 = f2tf32(v.y), h2 = f2tf32(v.z), h3 = f2tf32(v.w);
            unsigned l0 = f2tf32(v.x - __uint_as_float(h0));
            unsigned l1 = f2tf32(v.y - __uint_as_float(h1));
            unsigned l2 = f2tf32(v.z - __uint_as_float(h2));
            unsigned l3 = f2tf32(v.w - __uint_as_float(h3));
            *(uint4*)&Bh[r][c] = make_uint4(h0, h1, h2, h3);
            *(uint4*)&Bl[r][c] = make_uint4(l0, l1, l2, l3);
        }
        __syncthreads();

#pragma unroll
        for (int ks = 0; ks < 4; ++ks) {
            const int kk = ks * 8;
            unsigned afh[2][4], afl[2][4], bfh[4][2], bfl[4][2];
#pragma unroll
            for (int mf = 0; mf < 2; ++mf) {
                int r0 = mw + mf * 16;
                afh[mf][0] = Ah[r0 + g    ][kk + tg    ];
                afh[mf][1] = Ah[r0 + g + 8][kk + tg    ];
                afh[mf][2] = Ah[r0 + g    ][kk + tg + 4];
                afh[mf][3] = Ah[r0 + g + 8][kk + tg + 4];
                afl[mf][0] = Al[r0 + g    ][kk + tg    ];
                afl[mf][1] = Al[r0 + g + 8][kk + tg    ];
                afl[mf][2] = Al[r0 + g    ][kk + tg + 4];
                afl[mf][3] = Al[r0 + g + 8][kk + tg + 4];
            }
#pragma unroll
            for (int nf = 0; nf < 4; ++nf) {
                int c0 = nw + nf * 8;
                bfh[nf][0] = Bh[kk + tg    ][c0 + g];
                bfh[nf][1] = Bh[kk + tg + 4][c0 + g];
                bfl[nf][0] = Bl[kk + tg    ][c0 + g];
                bfl[nf][1] = Bl[kk + tg + 4][c0 + g];
            }
#pragma unroll
            for (int mf = 0; mf < 2; ++mf)
#pragma unroll
                for (int nf = 0; nf < 4; ++nf) {
                    mma_tf32(acc[mf][nf], afh[mf], bfl[nf]);
                    mma_tf32(acc[mf][nf], afl[mf], bfh[nf]);
                    mma_tf32(acc[mf][nf], afh[mf], bfh[nf]);
                }
        }
        __syncthreads();
    }

#pragma unroll
    for (int mf = 0; mf < 2; ++mf)
#pragma unroll
        for (int nf = 0; nf < 4; ++nf) {
            int row = bm + mw + mf * 16 + g;
            int col = bn + nw + nf * 8 + 2 * tg;
            *(float2*)&C[(size_t)row * M + col] =
                make_float2(acc[mf][nf][0], acc[mf][nf][1]);
            *(float2*)&C[(size_t)(row + 8) * M + col] =
                make_float2(acc[mf][nf][2], acc[mf][nf][3]);
        }
}

// ---------------- attention coefficients ----------------
__global__ void attn_kernel(const float* __restrict__ h,
                            const float* __restrict__ a_s,
                            const float* __restrict__ a_d,
                            float* __restrict__ als, float* __restrict__ ald,
                            int Nn, int H) {
    int w = (blockIdx.x * blockDim.x + threadIdx.x) >> 5;
    int lane = threadIdx.x & 31;
    if (w >= Nn * H) return;
    int node = w / H;
    int head = w - node * H;
    const float4* hp = (const float4*)(h + ((size_t)node * H + head) * FDIM);
    const float4* sp = (const float4*)(a_s + head * FDIM);
    const float4* dp = (const float4*)(a_d + head * FDIM);
    float4 hv = hp[lane], sv = sp[lane], dv = dp[lane];
    float s = hv.x * sv.x + hv.y * sv.y + hv.z * sv.z + hv.w * sv.w;
    float d = hv.x * dv.x + hv.y * dv.y + hv.z * dv.z + hv.w * dv.w;
#pragma unroll
    for (int o = 16; o > 0; o >>= 1) {
        s += __shfl_xor_sync(0xffffffffu, s, o);
        d += __shfl_xor_sync(0xffffffffu, d, o);
    }
    if (lane == 0) { als[w] = s; ald[w] = d; }
}

// ================= fused GAT aggregation (warp per node, CSR) =================
// agg_h = sum_e exp(e)*h[src] / sum_e exp(e)  (identical to max-subtracted softmax)
// then bias + leaky-relu; POOL variant scatters into graph pool instead.
template<int H, bool POOL>
__global__ void gat_agg_kernel(const int* __restrict__ rowptr, const int* __restrict__ csrc,
                               const float* __restrict__ hbuf,
                               const float* __restrict__ als, const float* __restrict__ ald,
                               const float* __restrict__ bias,
                               const int* __restrict__ batch,
                               float* __restrict__ outf, int Nn) {
    int w = (blockIdx.x * blockDim.x + threadIdx.x) >> 5;
    int lane = threadIdx.x & 31;
    if (w >= Nn) return;
    int beg = rowptr[w], end = rowptr[w + 1];

    float aldv = (lane < H) ? ald[(size_t)w * H + lane] : 0.0f;
    float den[H];
    float4 acc[H];
#pragma unroll
    for (int h = 0; h < H; ++h) { den[h] = 0.0f; acc[h] = make_float4(0, 0, 0, 0); }

    for (int i = beg; i < end; ++i) {
        int s = csrc[i];
        float alsv = (lane < H) ? als[(size_t)s * H + lane] : 0.0f;
        float exv = expf(lrelu(alsv + aldv));
        const float4* hp = (const float4*)(hbuf + (size_t)s * H * FDIM) + lane;
#pragma unroll
        for (int h = 0; h < H; ++h) {
            float ex = __shfl_sync(0xffffffffu, exv, h);
            float4 v = hp[h * 32];
            acc[h].x = fmaf(ex, v.x, acc[h].x);
            acc[h].y = fmaf(ex, v.y, acc[h].y);
            acc[h].z = fmaf(ex, v.z, acc[h].z);
            acc[h].w = fmaf(ex, v.w, acc[h].w);
            den[h] += ex;
        }
    }

    if (POOL) {
        float r = 1.0f / (den[0] + 1e-16f);
        float4 bv = *(const float4*)&bias[lane * 4];
        float4 v;
        v.x = lrelu(acc[0].x * r + bv.x);
        v.y = lrelu(acc[0].y * r + bv.y);
        v.z = lrelu(acc[0].z * r + bv.z);
        v.w = lrelu(acc[0].w * r + bv.w);
        float4* p = (float4*)(outf + (size_t)batch[w] * FDIM) + lane;
        asm volatile("red.global.add.v4.f32 [%0], {%1,%2,%3,%4};"
                     :: "l"(p), "f"(v.x), "f"(v.y), "f"(v.z), "f"(v.w) : "memory");
    } else {
        float4* op = (float4*)(outf + (size_t)w * H * FDIM) + lane;
#pragma unroll
        for (int h = 0; h < H; ++h) {
            float r = 1.0f / (den[h] + 1e-16f);
            float4 bv = *(const float4*)&bias[h * FDIM + lane * 4];
            float4 v;
            v.x = lrelu(acc[h].x * r + bv.x);
            v.y = lrelu(acc[h].y * r + bv.y);
            v.z = lrelu(acc[h].z * r + bv.z);
            v.w = lrelu(acc[h].w * r + bv.w);
            op[h * 32] = v;
        }
    }
}

// ---------------- pooling epilogue ----------------
__global__ void count_kernel(const int* __restrict__ batch, int* __restrict__ cnt, int Nn) {
    int n = blockIdx.x * blockDim.x + threadIdx.x;
    if (n < Nn) atomicAdd(&cnt[batch[n]], 1);
}
__global__ void out_kernel(const float* __restrict__ pool, const int* __restrict__ cnt,
                           float* __restrict__ out, int G) {
    int i = blockIdx.x * blockDim.x + threadIdx.x;
    if (i >= G * FDIM) return;
    int g = i >> 7;
    float c = (float)max(cnt[g], 1);
    out[i] = pool[i] / c;
}

// ---------------- host orchestration ----------------
extern "C" void kernel_launch(void* const* d_in, const int* in_sizes, int n_in,
                              void* d_out, int out_size) {
    const float* x   = (const float*)d_in[0];
    const int*   ei  = (const int*)d_in[1];
    const int*   bat = (const int*)d_in[2];
    const float* W1  = (const float*)d_in[3];
    const float* a1s = (const float*)d_in[4];
    const float* a1d = (const float*)d_in[5];
    const float* b1  = (const float*)d_in[6];
    const float* W2  = (const float*)d_in[7];
    const float* a2s = (const float*)d_in[8];
    const float* a2d = (const float*)d_in[9];
    const float* b2  = (const float*)d_in[10];
    const float* W3  = (const float*)d_in[11];
    const float* a3s = (const float*)d_in[12];
    const float* a3d = (const float*)d_in[13];
    const float* b3  = (const float*)d_in[14];

    int Nn = in_sizes[0] / FDIM;     // 200000
    int E  = in_sizes[1] / 2;        // 1600000
    int Et = E + Nn;
    const int* srcs = ei;
    const int* dsts = ei + E;

    float *hbuf, *feat, *als, *ald, *pool;
    int *cnt, *deg, *rowptr, *woff, *bsum, *csrc;
    cudaGetSymbolAddress((void**)&hbuf,   g_h);
    cudaGetSymbolAddress((void**)&feat,   g_feat);
    cudaGetSymbolAddress((void**)&als,    g_als);
    cudaGetSymbolAddress((void**)&ald,    g_ald);
    cudaGetSymbolAddress((void**)&pool,   g_pool);
    cudaGetSymbolAddress((void**)&cnt,    g_cnt);
    cudaGetSymbolAddress((void**)&deg,    g_deg);
    cudaGetSymbolAddress((void**)&rowptr, g_rowptr);
    cudaGetSymbolAddress((void**)&woff,   g_woff);
    cudaGetSymbolAddress((void**)&bsum,   g_bsum);
    cudaGetSymbolAddress((void**)&csrc,   g_csrc);

    // ---- CSR build (once per call) ----
    zero_i<<<512, 256>>>(deg, (size_t)Nn);
    deg_kernel<<<(Et + 255) / 256, 256>>>(dsts, E, Nn, deg);
    scan1_kernel<<<SCAN_NB, SCAN_B>>>(deg, rowptr, bsum, Nn);
    scan2_kernel<<<1, 256>>>(bsum, SCAN_NB);
    scan3_kernel<<<SCAN_NB, SCAN_B>>>(rowptr, woff, bsum, Nn, Et);
    scatter_kernel<<<(Et + 255) / 256, 256>>>(srcs, dsts, E, Nn, woff, csrc);

    const unsigned aggGrid = (unsigned)(((size_t)Nn * 32 + 255) / 256);

    // ---- layer 1: 128 -> 3x128 ----
    {
        dim3 ggrid(384 / GBN, Nn / GBM);
        gemm_tf32_kernel<<<ggrid, 128>>>(x, W1, hbuf, Nn, 128, 384);
        long long nwt = (long long)Nn * 3 * 32;
        attn_kernel<<<(unsigned)((nwt + 255) / 256), 256>>>(hbuf, a1s, a1d, als, ald, Nn, 3);
        gat_agg_kernel<3, false><<<aggGrid, 256>>>(rowptr, csrc, hbuf, als, ald, b1, bat, feat, Nn);
    }
    // ---- layer 2: 384 -> 3x128 ----
    {
        dim3 ggrid(384 / GBN, Nn / GBM);
        gemm_tf32_kernel<<<ggrid, 128>>>(feat, W2, hbuf, Nn, 384, 384);
        long long nwt = (long long)Nn * 3 * 32;
        attn_kernel<<<(unsigned)((nwt + 255) / 256), 256>>>(hbuf, a2s, a2d, als, ald, Nn, 3);
        gat_agg_kernel<3, false><<<aggGrid, 256>>>(rowptr, csrc, hbuf, als, ald, b2, bat, feat, Nn);
    }
    // ---- layer 3: 384 -> 1x128 + fused pooling scatter ----
    {
        zero_f<<<512, 256>>>(pool, (size_t)NG * FDIM);
        zero_i<<<32, 256>>>(cnt, (size_t)NG);
        dim3 ggrid(128 / GBN, Nn / GBM);
        gemm_tf32_kernel<<<ggrid, 128>>>(feat, W3, hbuf, Nn, 384, 128);
        long long nwt = (long long)Nn * 1 * 32;
        attn_kernel<<<(unsigned)((nwt + 255) / 256), 256>>>(hbuf, a3s, a3d, als, ald, Nn, 1);
        gat_agg_kernel<1, true><<<aggGrid, 256>>>(rowptr, csrc, hbuf, als, ald, b3, bat, pool, Nn);
    }

    // ---- output ----
    count_kernel<<<(Nn + 255) / 256, 256>>>(bat, cnt, Nn);
    out_kernel<<<(NG * FDIM + 255) / 256, 256>>>(pool, cnt, (float*)d_out, NG);
}